// round 2
// baseline (speedup 1.0000x reference)
#include <cuda_runtime.h>

#define B_   64
#define NGF  256
#define S_   2048
#define ENCH 512
#define ZD   64
#define DECH 256

#define TS 64   // s-tile rows per block
#define TH 64   // h chunk
#define KT 32   // k tile for gemm1
#define NTILES (S_/TS)   // 32

// Scratch (no allocations allowed)
__device__ float g_w[B_*NGF];            // [B,256] masked row sums
__device__ float g_c[B_*ENCH];           // [B,512] c_b = w@W1[256:] + b1
__device__ float g_zpart[B_*NTILES*ZD];  // per-(b,tile) partial z

// ---------------------------------------------------------------------------
// Kernel A: w[b,g] = sum_{s<len[b]} u[b,g,s].  One warp per row.
// ---------------------------------------------------------------------------
__global__ void rowsum_kernel(const float* __restrict__ u,
                              const int* __restrict__ lengths) {
    int warp = (blockIdx.x * blockDim.x + threadIdx.x) >> 5;
    int lane = threadIdx.x & 31;
    if (warp >= B_ * NGF) return;
    int b = warp >> 8;
    int len = lengths[b];
    const float* row = u + (size_t)warp * S_;
    float sum = 0.f;
    for (int s = lane; s < len; s += 32) sum += row[s];
    #pragma unroll
    for (int o = 16; o > 0; o >>= 1) sum += __shfl_down_sync(0xffffffffu, sum, o);
    if (lane == 0) g_w[warp] = sum;
}

// ---------------------------------------------------------------------------
// Kernel B: c[b,h] = b1[h] + sum_g w[b,g] * W1[256+g, h].  Block per batch.
// ---------------------------------------------------------------------------
__global__ void cvec_kernel(const float* __restrict__ W1,
                            const float* __restrict__ b1) {
    __shared__ float wsh[NGF];
    int b = blockIdx.x;
    int h = threadIdx.x;          // 512 threads
    if (h < NGF) wsh[h] = g_w[b * NGF + h];
    __syncthreads();
    float acc = b1[h];
    const float* Wp = W1 + (size_t)NGF * ENCH + h;   // rows 256..511
    #pragma unroll 8
    for (int g = 0; g < NGF; g++) acc = fmaf(wsh[g], Wp[(size_t)g * ENCH], acc);
    g_c[b * ENCH + h] = acc;
}

// ---------------------------------------------------------------------------
// Kernel C (main): per (b, s-tile of 64) block.
//   h[s,:]  = relu(u_t[s,:]@W1[:256] + c_b)       (GEMM1, K=256)
//   z[s,:]  = relu(h[s,:]@W2 + b2)                (GEMM2, K=512 in 64-chunks)
//   zpart   = sum over valid s of z[s,:]
// 256 threads, 16x16 thread grid, 4x4 register micro-tiles.
// ---------------------------------------------------------------------------
__global__ void __launch_bounds__(256)
main_kernel(const float* __restrict__ u, const int* __restrict__ lengths,
            const float* __restrict__ W1, const float* __restrict__ W2,
            const float* __restrict__ b2) {
    extern __shared__ float smem[];
    float* u_s  = smem;                    // [256][TS]      64KB
    float* w_s  = u_s + NGF * TS;          // [KT][TH]        8KB
    float* h_s  = w_s + KT * TH;           // [TS][TH+4]     17KB
    float* w2_s = h_s + TS * (TH + 4);     // [TH][ZD]       16KB
    float* red  = w2_s + TH * ZD;          // [16][ZD+4]      4.3KB

    int b = blockIdx.y, tile = blockIdx.x;
    int len = lengths[b];
    int s0 = tile * TS;
    if (s0 >= len) return;                 // uniform per block: sync-safe

    int tid = threadIdx.x;

    // load u tile: u[b, g, s0 + 0..63] -> u_s[g][s]
    const float* ub = u + ((size_t)b * NGF) * S_ + s0;
    #pragma unroll
    for (int i = tid; i < NGF * (TS / 4); i += 256) {   // 16 iters/thread
        int g = i >> 4, q = i & 15;
        float4 v = *(const float4*)(ub + (size_t)g * S_ + q * 4);
        *(float4*)&u_s[g * TS + q * 4] = v;
    }

    int tx = tid & 15, ty = tid >> 4;
    int srow = ty * 4, hcol = tx * 4, zcol = tx * 4;

    float zacc[4][4];
    #pragma unroll
    for (int i = 0; i < 4; i++)
        #pragma unroll
        for (int j = 0; j < 4; j++) zacc[i][j] = 0.f;

    const float* cb = g_c + b * ENCH;
    __syncthreads();   // u_s ready

    for (int hc = 0; hc < ENCH; hc += TH) {
        float acc[4][4];
        #pragma unroll
        for (int i = 0; i < 4; i++)
            #pragma unroll
            for (int j = 0; j < 4; j++) acc[i][j] = 0.f;

        // ---- GEMM1 over K=256 in KT tiles ----
        for (int k0 = 0; k0 < NGF; k0 += KT) {
            #pragma unroll
            for (int i = tid; i < KT * TH / 4; i += 256) {  // 2 iters/thread
                int kk = i >> 4, hq = i & 15;
                *(float4*)&w_s[kk * TH + hq * 4] =
                    *(const float4*)&W1[(size_t)(k0 + kk) * ENCH + hc + hq * 4];
            }
            __syncthreads();
            #pragma unroll 8
            for (int kk = 0; kk < KT; kk++) {
                float4 a  = *(float4*)&u_s[(k0 + kk) * TS + srow];
                float4 bb = *(float4*)&w_s[kk * TH + hcol];
                float av[4] = {a.x, a.y, a.z, a.w};
                float bv[4] = {bb.x, bb.y, bb.z, bb.w};
                #pragma unroll
                for (int i = 0; i < 4; i++)
                    #pragma unroll
                    for (int j = 0; j < 4; j++)
                        acc[i][j] = fmaf(av[i], bv[j], acc[i][j]);
            }
            __syncthreads();
        }

        // relu(+c_b) -> h_s
        #pragma unroll
        for (int i = 0; i < 4; i++)
            #pragma unroll
            for (int j = 0; j < 4; j++) {
                float v = acc[i][j] + cb[hc + hcol + j];
                h_s[(srow + i) * (TH + 4) + hcol + j] = fmaxf(v, 0.f);
            }

        // load W2 chunk
        #pragma unroll
        for (int i = tid; i < TH * ZD / 4; i += 256) {   // 4 iters/thread
            int k = i >> 4, zq = i & 15;
            *(float4*)&w2_s[k * ZD + zq * 4] =
                *(const float4*)&W2[(size_t)(hc + k) * ZD + zq * 4];
        }
        __syncthreads();

        // ---- GEMM2 partial: zacc += h_chunk @ W2_chunk ----
        #pragma unroll 8
        for (int k = 0; k < TH; k++) {
            float av[4];
            #pragma unroll
            for (int i = 0; i < 4; i++) av[i] = h_s[(srow + i) * (TH + 4) + k];
            float4 bb = *(float4*)&w2_s[k * ZD + zcol];
            float bv[4] = {bb.x, bb.y, bb.z, bb.w};
            #pragma unroll
            for (int i = 0; i < 4; i++)
                #pragma unroll
                for (int j = 0; j < 4; j++)
                    zacc[i][j] = fmaf(av[i], bv[j], zacc[i][j]);
        }
        __syncthreads();
    }

    // epilogue: relu(z + b2), mask s >= len, sum over the 64 s-rows
    float4 b2v = *(const float4*)&b2[zcol];
    float b2a[4] = {b2v.x, b2v.y, b2v.z, b2v.w};
    float part[4] = {0.f, 0.f, 0.f, 0.f};
    #pragma unroll
    for (int i = 0; i < 4; i++) {
        if (s0 + srow + i < len) {
            #pragma unroll
            for (int j = 0; j < 4; j++)
                part[j] += fmaxf(zacc[i][j] + b2a[j], 0.f);
        }
    }
    #pragma unroll
    for (int j = 0; j < 4; j++) red[ty * (ZD + 4) + zcol + j] = part[j];
    __syncthreads();
    if (tid < ZD) {
        float s = 0.f;
        #pragma unroll
        for (int t = 0; t < 16; t++) s += red[t * (ZD + 4) + tid];
        g_zpart[(b * NTILES + tile) * ZD + tid] = s;
    }
}

// ---------------------------------------------------------------------------
// Kernel D: z = sum of partials; d = relu(z@W3+b3); y = d@W4 + b4.
// One block per batch, 256 threads (= DECH).
// ---------------------------------------------------------------------------
__global__ void tail_kernel(const int* __restrict__ lengths,
                            const float* __restrict__ W3, const float* __restrict__ b3,
                            const float* __restrict__ W4, const float* __restrict__ b4,
                            float* __restrict__ y) {
    __shared__ float z_b[ZD];
    __shared__ float redc[DECH];
    int b = blockIdx.x;
    int tid = threadIdx.x;
    int len = lengths[b];
    int ntiles = (len + TS - 1) / TS;
    if (tid < ZD) {
        float s = 0.f;
        for (int t = 0; t < ntiles; t++) s += g_zpart[(b * NTILES + t) * ZD + tid];
        z_b[tid] = s;
    }
    __syncthreads();
    float acc = b3[tid];
    #pragma unroll 8
    for (int k = 0; k < ZD; k++) acc = fmaf(z_b[k], W3[k * DECH + tid], acc);
    redc[tid] = fmaxf(acc, 0.f) * W4[tid];
    __syncthreads();
    #pragma unroll
    for (int o = DECH / 2; o > 0; o >>= 1) {
        if (tid < o) redc[tid] += redc[tid + o];
        __syncthreads();
    }
    if (tid == 0) y[b] = redc[0] + b4[0];
}

// ---------------------------------------------------------------------------
extern "C" void kernel_launch(void* const* d_in, const int* in_sizes, int n_in,
                              void* d_out, int out_size) {
    const float* u       = (const float*)d_in[0];
    const int*   lengths = (const int*)  d_in[1];
    const float* W1      = (const float*)d_in[2];
    const float* b1      = (const float*)d_in[3];
    const float* W2      = (const float*)d_in[4];
    const float* b2      = (const float*)d_in[5];
    const float* W3      = (const float*)d_in[6];
    const float* b3      = (const float*)d_in[7];
    const float* W4      = (const float*)d_in[8];
    const float* b4      = (const float*)d_in[9];
    float* y = (float*)d_out;

    static int smem_set = 0;
    size_t smem = (size_t)(NGF * TS + KT * TH + TS * (TH + 4) + TH * ZD + 16 * (ZD + 4))
                  * sizeof(float);
    if (!smem_set) {
        cudaFuncSetAttribute((const void*)main_kernel,
                             cudaFuncAttributeMaxDynamicSharedMemorySize, (int)smem);
        smem_set = 1;
    }

    rowsum_kernel<<<(B_ * NGF) / 8, 256>>>(u, lengths);
    cvec_kernel<<<B_, ENCH>>>(W1, b1);

    dim3 grid(NTILES, B_);
    main_kernel<<<grid, 256, smem>>>(u, lengths, W1, W2, b2);

    tail_kernel<<<B_, DECH>>>(lengths, W3, b3, W4, b4, y);
}